// round 1
// baseline (speedup 1.0000x reference)
#include <cuda_runtime.h>
#include <math.h>

#define BB   64
#define CC   512
#define HW   784
#define NREG 64
#define TT   56      // pixels per tile in main kernel
#define NTILE 14     // 784 / 56
#define GT   224     // threads in main kernel (16 n-groups x 14 t-groups)

// ---------------- scratch (static device memory; no allocation) ----------------
__device__ __align__(256) float g_scale[CC];
__device__ __align__(256) float g_shift[CC];
__device__ __align__(256) float g_rowsum[BB*CC];
__device__ __align__(256) float g_rowsq [BB*CC];
__device__ __align__(256) float g_a1   [BB*CC];
__device__ __align__(256) float g_att2 [BB*HW];
__device__ __align__(256) float g_srean[(size_t)BB*NREG*HW];   // 12.8 MB
__device__ __align__(256) float g_score[BB*NREG];
__device__ __align__(256) float g_feat [BB*CC];
__device__ __align__(256) float g_l3[BB];
__device__ __align__(256) float g_ls[BB];

// ---------------- reduction helpers ----------------
__device__ __forceinline__ float wredsum(float v){
    #pragma unroll
    for (int o = 16; o; o >>= 1) v += __shfl_down_sync(0xffffffffu, v, o);
    return v;
}
__device__ __forceinline__ float wredmax(float v){
    #pragma unroll
    for (int o = 16; o; o >>= 1) v = fmaxf(v, __shfl_down_sync(0xffffffffu, v, o));
    return v;
}
// blockDim.x == 256 assumed
__device__ __forceinline__ float blockRedSum256(float v, float* red){
    int lane = threadIdx.x & 31, w = threadIdx.x >> 5;
    v = wredsum(v);
    if (lane == 0) red[w] = v;
    __syncthreads();
    if (threadIdx.x == 0){
        float s = 0.f;
        #pragma unroll
        for (int i = 0; i < 8; i++) s += red[i];
        red[0] = s;
    }
    __syncthreads();
    float r = red[0];
    __syncthreads();
    return r;
}
__device__ __forceinline__ float blockRedMax256(float v, float* red){
    int lane = threadIdx.x & 31, w = threadIdx.x >> 5;
    v = wredmax(v);
    if (lane == 0) red[w] = v;
    __syncthreads();
    if (threadIdx.x == 0){
        float s = red[0];
        #pragma unroll
        for (int i = 1; i < 8; i++) s = fmaxf(s, red[i]);
        red[0] = s;
    }
    __syncthreads();
    float r = red[0];
    __syncthreads();
    return r;
}

// ---------------- K1a: per-(b,c) row sums (for BN stats + pooled) ----------------
__global__ void k_rowsum(const float* __restrict__ v){
    int w = (blockIdx.x * blockDim.x + threadIdx.x) >> 5;  // global warp = b*C + c
    int lane = threadIdx.x & 31;
    if (w >= BB*CC) return;
    const float4* row = (const float4*)(v + (size_t)w * HW);
    float p = 0.f, q = 0.f;
    #pragma unroll
    for (int i = 0; i < 7; i++){
        int idx = lane + i*32;
        if (idx < 196){
            float4 x = row[idx];
            p += x.x + x.y + x.z + x.w;
            q += x.x*x.x + x.y*x.y + x.z*x.z + x.w*x.w;
        }
    }
    p = wredsum(p); q = wredsum(q);
    if (lane == 0){ g_rowsum[w] = p; g_rowsq[w] = q; }
}

// ---------------- K1b: BN scale/shift per channel ----------------
__global__ void k_bnparam(const float* __restrict__ gamma, const float* __restrict__ beta){
    int c = blockIdx.x;  // 512 blocks, 64 threads
    int b = threadIdx.x;
    __shared__ float sp[BB], sq[BB];
    sp[b] = g_rowsum[b*CC + c];
    sq[b] = g_rowsq [b*CC + c];
    __syncthreads();
    if (b == 0){
        float P = 0.f, Q = 0.f;
        for (int i = 0; i < BB; i++){ P += sp[i]; Q += sq[i]; }
        const float inv = 1.0f / (float)(BB*HW);
        float mu  = P * inv;
        float var = Q * inv - mu*mu;
        float sc  = gamma[c] * rsqrtf(var + 1e-5f);
        g_scale[c] = sc;
        g_shift[c] = beta[c] - mu * sc;
    }
}

// ---------------- K2: a1 = l2norm(t_feature) rows ----------------
__global__ void k_a1(const float* __restrict__ t){
    int b = blockIdx.x; int tid = threadIdx.x;  // 128 threads
    float s = 0.f;
    for (int c = tid; c < CC; c += 128){ float x = t[b*CC + c]; s += x*x; }
    __shared__ float red[4];
    __shared__ float sinv;
    float ws = wredsum(s);
    if ((tid & 31) == 0) red[tid >> 5] = ws;
    __syncthreads();
    if (tid == 0) sinv = 1.0f / fmaxf(sqrtf(red[0]+red[1]+red[2]+red[3]), 1e-12f);
    __syncthreads();
    for (int c = tid; c < CC; c += 128) g_a1[b*CC + c] = t[b*CC + c] * sinv;
}

// ---------------- K3: fused main pass ----------------
// Per block: batch b, 56-pixel tile. Loads mvsa tile [512 x 56] to smem,
// computes att_map2 per pixel, srea = W @ mvsa + bias (4x4 register GEMM),
// L2-normalizes srea over n, writes srea_n.
__global__ void __launch_bounds__(GT, 1) k_main(
    const float* __restrict__ v,
    const float* __restrict__ w,
    const float* __restrict__ wb)
{
    extern __shared__ float Xs[];           // CC * TT floats = 114688 B
    __shared__ float pn[16*TT];
    __shared__ float pr[4*TT], pa[4*TT];
    __shared__ float sinv[TT];

    int b    = blockIdx.x / NTILE;
    int tile = blockIdx.x % NTILE;
    int hw0  = tile * TT;
    int tid  = threadIdx.x;

    // ---- fill smem with mvsa tile ----
    {
        int t  = tid % TT;
        int c0 = tid / TT;  // 0..3
        const float* base = v + (size_t)b*CC*HW + hw0 + t;
        #pragma unroll 8
        for (int c = c0; c < CC; c += 4){
            Xs[c*TT + t] = base[(size_t)c*HW] * g_scale[c] + g_shift[c];
        }
    }
    __syncthreads();

    // ---- per-pixel ||mvsa|| and att_map2 = dot(mvsa, a1)/||mvsa|| ----
    {
        int t = tid % TT;
        int s = tid / TT;
        float nr = 0.f, ad = 0.f;
        const float* a1b = g_a1 + b*CC;
        #pragma unroll 4
        for (int c = s*128; c < s*128 + 128; c++){
            float x = Xs[c*TT + t];
            nr += x*x;
            ad += x * a1b[c];
        }
        pr[s*TT + t] = nr;
        pa[s*TT + t] = ad;
    }
    __syncthreads();
    if (tid < TT){
        float nr = pr[tid] + pr[TT+tid] + pr[2*TT+tid] + pr[3*TT+tid];
        float ad = pa[tid] + pa[TT+tid] + pa[2*TT+tid] + pa[3*TT+tid];
        float inv = 1.0f / fmaxf(sqrtf(nr), 1e-12f);
        g_att2[b*HW + hw0 + tid] = ad * inv;
    }

    // ---- GEMM: srea[64][56] = W[64,512] @ Xs[512,56] + bias ----
    int tn = tid / NTILE;        // 0..15
    int tt = tid % NTILE;        // 0..13
    int n0 = tn*4, t0 = tt*4;

    float acc[4][4];
    #pragma unroll
    for (int i = 0; i < 4; i++){
        float bi = wb[n0 + i];
        #pragma unroll
        for (int j = 0; j < 4; j++) acc[i][j] = bi;
    }

    const float4* w0 = (const float4*)(w + (size_t)(n0+0)*CC);
    const float4* w1 = (const float4*)(w + (size_t)(n0+1)*CC);
    const float4* w2 = (const float4*)(w + (size_t)(n0+2)*CC);
    const float4* w3 = (const float4*)(w + (size_t)(n0+3)*CC);

    #pragma unroll 2
    for (int k4 = 0; k4 < CC/4; k4++){
        float4 wv[4];
        wv[0] = w0[k4]; wv[1] = w1[k4]; wv[2] = w2[k4]; wv[3] = w3[k4];
        float4 xv[4];
        #pragma unroll
        for (int kk = 0; kk < 4; kk++)
            xv[kk] = *(const float4*)&Xs[(k4*4 + kk)*TT + t0];
        #pragma unroll
        for (int kk = 0; kk < 4; kk++){
            float x0 = ((const float*)&xv[kk])[0];
            float x1 = ((const float*)&xv[kk])[1];
            float x2 = ((const float*)&xv[kk])[2];
            float x3 = ((const float*)&xv[kk])[3];
            #pragma unroll
            for (int i = 0; i < 4; i++){
                float wi = ((const float*)&wv[i])[kk];
                acc[i][0] = fmaf(wi, x0, acc[i][0]);
                acc[i][1] = fmaf(wi, x1, acc[i][1]);
                acc[i][2] = fmaf(wi, x2, acc[i][2]);
                acc[i][3] = fmaf(wi, x3, acc[i][3]);
            }
        }
    }

    // ---- per-pixel L2 norm over n (64 regions) ----
    #pragma unroll
    for (int j = 0; j < 4; j++){
        float ss = acc[0][j]*acc[0][j] + acc[1][j]*acc[1][j]
                 + acc[2][j]*acc[2][j] + acc[3][j]*acc[3][j];
        pn[tn*TT + t0 + j] = ss;
    }
    __syncthreads();
    if (tid < TT){
        float ssum = 0.f;
        #pragma unroll
        for (int g = 0; g < 16; g++) ssum += pn[g*TT + tid];
        sinv[tid] = 1.0f / fmaxf(sqrtf(ssum), 1e-12f);
    }
    __syncthreads();

    float* outb = g_srean + ((size_t)b*NREG)*HW + hw0;
    #pragma unroll
    for (int i = 0; i < 4; i++){
        float4 o;
        o.x = acc[i][0] * sinv[t0+0];
        o.y = acc[i][1] * sinv[t0+1];
        o.z = acc[i][2] * sinv[t0+2];
        o.w = acc[i][3] * sinv[t0+3];
        *(float4*)&outb[(size_t)(n0+i)*HW + t0] = o;
    }
}

// ---------------- K4: score[b,n] = sum_hw srea_n * att_map2 ----------------
__global__ void k_score(){
    int b = blockIdx.x; int tid = threadIdx.x;  // 256 threads
    __shared__ float att[HW];
    for (int h = tid; h < HW; h += 256) att[h] = g_att2[b*HW + h];
    __syncthreads();
    int warp = tid >> 5, lane = tid & 31;
    for (int n = warp; n < NREG; n += 8){
        const float* r = g_srean + ((size_t)b*NREG + n)*HW;
        float s = 0.f;
        for (int h = lane; h < HW; h += 32) s += r[h] * att[h];
        s = wredsum(s);
        if (lane == 0) g_score[b*NREG + n] = s;
    }
}

// ---------------- K5: feat = pooled @ fc1_w^T + fc1_b ----------------
#define PS 513
__global__ void k_feat(const float* __restrict__ fw, const float* __restrict__ fb){
    extern __shared__ float sm[];
    float* pooled = sm;              // 64 * 513
    float* ws     = sm + BB*PS;      // 8 * 513
    int tid = threadIdx.x;           // 256
    int o0 = blockIdx.x * 8;         // 64 blocks

    for (int idx = tid; idx < BB*CC; idx += 256){
        int bb = idx >> 9, cc = idx & 511;
        pooled[bb*PS + cc] = g_rowsum[idx] * (1.0f/(float)HW) * g_scale[cc] + g_shift[cc];
    }
    for (int idx = tid; idx < 8*CC; idx += 256){
        int oo = idx >> 9, cc = idx & 511;
        ws[oo*PS + cc] = fw[(size_t)(o0+oo)*CC + cc];
    }
    __syncthreads();

    #pragma unroll
    for (int r = 0; r < 2; r++){
        int p  = tid*2 + r;
        int bb = p >> 3, oo = p & 7;
        float s = 0.f;
        #pragma unroll 8
        for (int k = 0; k < CC; k++) s = fmaf(pooled[bb*PS + k], ws[oo*PS + k], s);
        g_feat[bb*CC + (o0+oo)] = s + fb[o0+oo];
    }
}

// ---------------- K6: per-batch stats + loss terms ----------------
__global__ void k_loss(){
    int b = blockIdx.x; int tid = threadIdx.x;  // 256 threads
    __shared__ int s_nmax;
    __shared__ float red[8];
    if (tid == 0){
        const float* sc = g_score + b*NREG;
        float m = 0.f;
        for (int n = 0; n < NREG; n++) m += sc[n];
        m *= (1.0f/NREG);
        float bmax = sc[0]; int imax = 0;
        float sp = 0.f, sq = 0.f;
        for (int n = 0; n < NREG; n++){
            float x = sc[n];
            if (x > bmax){ bmax = x; imax = n; }
            if (x > m) sp += x; else sq += x;
        }
        sp *= (1.0f/NREG); sq *= (1.0f/NREG);
        float d = sq - sp;
        g_l3[b] = (d > 20.0f) ? d : log1pf(expf(d));
        s_nmax = imax;
    }
    __syncthreads();

    const float* pl = g_att2 + b*HW;
    const float* ql = g_srean + ((size_t)b*NREG + s_nmax)*HW;
    const float qs = 1.0f/(float)NREG;   // srea_P = srea_n[nmax] / 64

    float mp = -1e30f, mq = -1e30f;
    for (int h = tid; h < HW; h += 256){
        mp = fmaxf(mp, pl[h]);
        mq = fmaxf(mq, ql[h]*qs);
    }
    mp = blockRedMax256(mp, red);
    mq = blockRedMax256(mq, red);

    float ep = 0.f, eq = 0.f;
    for (int h = tid; h < HW; h += 256){
        ep += expf(pl[h] - mp);
        eq += expf(ql[h]*qs - mq);
    }
    ep = blockRedSum256(ep, red);
    eq = blockRedSum256(eq, red);
    float lsep = mp + logf(ep);
    float lseq = mq + logf(eq);

    float S = 0.f;
    for (int h = tid; h < HW; h += 256){
        float lp = pl[h] - lsep;
        float lq = ql[h]*qs - lseq;
        float p  = expf(lp);
        float q  = expf(lq);
        float lm = logf(0.5f*(p + q));
        S += p*(lp - lm) + q*(lq - lm);
    }
    S = blockRedSum256(S, red);
    if (tid == 0) g_ls[b] = S;
}

// ---------------- K7: dual_sim = l2norm(feat) @ a1^T ----------------
__global__ void k_dual(float* __restrict__ out){
    int b = blockIdx.x; int tid = threadIdx.x;  // 128 threads
    __shared__ float fr[CC];
    __shared__ float red[4];
    __shared__ float sinvb;
    float ss = 0.f;
    for (int c = tid; c < CC; c += 128){ float x = g_feat[b*CC + c]; fr[c] = x; ss += x*x; }
    ss = wredsum(ss);
    if ((tid & 31) == 0) red[tid >> 5] = ss;
    __syncthreads();
    if (tid == 0) sinvb = 1.0f / fmaxf(sqrtf(red[0]+red[1]+red[2]+red[3]), 1e-12f);
    __syncthreads();
    int warp = tid >> 5, lane = tid & 31;
    for (int j = warp; j < BB; j += 4){
        const float* a = g_a1 + j*CC;
        float s = 0.f;
        for (int c = lane; c < CC; c += 32) s += fr[c] * a[c];
        s = wredsum(s);
        if (lane == 0) out[b*BB + j] = s * sinvb;
    }
}

// ---------------- K8: final scalar loss ----------------
__global__ void k_final(float* __restrict__ out, int li){
    int t = threadIdx.x;  // 64 threads
    __shared__ float r3[BB], rls[BB];
    r3[t] = g_l3[t]; rls[t] = g_ls[t];
    __syncthreads();
    if (t == 0){
        float a = 0.f, c2 = 0.f;
        for (int i = 0; i < BB; i++){ a += r3[i]; c2 += rls[i]; }
        float loss3 = a / (float)BB;
        float loss2 = 0.5f * c2 / (float)BB;
        out[li] = 0.1f*loss3 + 0.1f*loss2;
    }
}

// ---------------- launcher ----------------
extern "C" void kernel_launch(void* const* d_in, const int* in_sizes, int n_in,
                              void* d_out, int out_size){
    const float* v     = (const float*)d_in[0];
    const float* t     = (const float*)d_in[1];
    const float* cw    = (const float*)d_in[2];
    const float* cb    = (const float*)d_in[3];
    const float* gamma = (const float*)d_in[4];
    const float* beta  = (const float*)d_in[5];
    const float* fw    = (const float*)d_in[6];
    const float* fb    = (const float*)d_in[7];
    float* out = (float*)d_out;

    cudaFuncSetAttribute(k_main, cudaFuncAttributeMaxDynamicSharedMemorySize, CC*TT*4);
    cudaFuncSetAttribute(k_feat, cudaFuncAttributeMaxDynamicSharedMemorySize, (BB*PS + 8*PS)*4);

    k_rowsum<<<(BB*CC)/8, 256>>>(v);
    k_bnparam<<<CC, 64>>>(gamma, beta);
    k_a1<<<BB, 128>>>(t);
    k_main<<<BB*NTILE, GT, CC*TT*4>>>(v, cw, cb);
    k_score<<<BB, 256>>>();
    k_feat<<<64, 256, (BB*PS + 8*PS)*4>>>(fw, fb);
    k_loss<<<BB, 256>>>();
    k_dual<<<BB, 128>>>(out);
    int li = (out_size > 4096) ? 4096 : (out_size - 1);
    k_final<<<1, 64>>>(out, li);
}

// round 2
// speedup vs baseline: 1.2369x; 1.2369x over previous
#include <cuda_runtime.h>
#include <math.h>

#define BB   64
#define CC   512
#define HW   784
#define NREG 64
#define TT   56
#define NTILE 14
#define GT   448
#define XS_BYTES 129024

// ---------------- scratch (static device memory; no allocation) ----------------
__device__ __align__(256) float g_scale[CC];
__device__ __align__(256) float g_shift[CC];
__device__ __align__(256) float g_rowsum[BB*CC];
__device__ __align__(256) float g_rowsq [BB*CC];
__device__ __align__(256) float g_a1   [BB*CC];
__device__ __align__(256) float g_att2 [BB*HW];
__device__ __align__(256) float g_srean[(size_t)BB*NREG*HW];   // 12.8 MB
__device__ __align__(256) float g_scorep[BB*NTILE*NREG];
__device__ __align__(256) float g_feat [BB*CC];
__device__ __align__(256) float g_l3[BB];
__device__ __align__(256) float g_ls[BB];

// ---------------- helpers ----------------
__device__ __forceinline__ float wredsum(float v){
    #pragma unroll
    for (int o = 16; o; o >>= 1) v += __shfl_down_sync(0xffffffffu, v, o);
    return v;
}
__device__ __forceinline__ float wredmax(float v){
    #pragma unroll
    for (int o = 16; o; o >>= 1) v = fmaxf(v, __shfl_down_sync(0xffffffffu, v, o));
    return v;
}
__device__ __forceinline__ float blockRedSum256(float v, float* red){
    int lane = threadIdx.x & 31, w = threadIdx.x >> 5;
    v = wredsum(v);
    if (lane == 0) red[w] = v;
    __syncthreads();
    if (threadIdx.x == 0){
        float s = 0.f;
        #pragma unroll
        for (int i = 0; i < 8; i++) s += red[i];
        red[0] = s;
    }
    __syncthreads();
    float r = red[0];
    __syncthreads();
    return r;
}
__device__ __forceinline__ float blockRedMax256(float v, float* red){
    int lane = threadIdx.x & 31, w = threadIdx.x >> 5;
    v = wredmax(v);
    if (lane == 0) red[w] = v;
    __syncthreads();
    if (threadIdx.x == 0){
        float s = red[0];
        #pragma unroll
        for (int i = 1; i < 8; i++) s = fmaxf(s, red[i]);
        red[0] = s;
    }
    __syncthreads();
    float r = red[0];
    __syncthreads();
    return r;
}

// packed fp32x2 FMA (Blackwell)
#define FMA2(d,a,b) asm("fma.rn.f32x2 %0, %1, %2, %0;" : "+l"(d) : "l"(a), "l"(b))
__device__ __forceinline__ float2 up2(unsigned long long v){
    float2 r; asm("mov.b64 {%0, %1}, %2;" : "=f"(r.x), "=f"(r.y) : "l"(v)); return r;
}

// swizzled smem index for element (c, t):
// 16B unit u = (c>>1)*28 + (t>>1); unit holds {x[2k][t0], x[2k+1][t0], x[2k][t0+1], x[2k+1][t0+1]}
__device__ __forceinline__ int sidx(int c, int t){
    int u = (c>>1)*28 + (t>>1);
    return ((u + (u>>3))<<2) + ((t&1)<<1) + (c&1);
}

// ---------------- K1a: per-(b,c) row sums ----------------
__global__ void k_rowsum(const float* __restrict__ v){
    int w = (blockIdx.x * blockDim.x + threadIdx.x) >> 5;
    int lane = threadIdx.x & 31;
    if (w >= BB*CC) return;
    const float4* row = (const float4*)(v + (size_t)w * HW);
    float p = 0.f, q = 0.f;
    #pragma unroll
    for (int i = 0; i < 7; i++){
        int idx = lane + i*32;
        if (idx < 196){
            float4 x = row[idx];
            p += x.x + x.y + x.z + x.w;
            q += x.x*x.x + x.y*x.y + x.z*x.z + x.w*x.w;
        }
    }
    p = wredsum(p); q = wredsum(q);
    if (lane == 0){ g_rowsum[w] = p; g_rowsq[w] = q; }
}

// ---------------- K1b: BN scale/shift per channel ----------------
__global__ void k_bnparam(const float* __restrict__ gamma, const float* __restrict__ beta){
    int c = blockIdx.x;
    int b = threadIdx.x;
    __shared__ float sp[BB], sq[BB];
    sp[b] = g_rowsum[b*CC + c];
    sq[b] = g_rowsq [b*CC + c];
    __syncthreads();
    if (b == 0){
        float P = 0.f, Q = 0.f;
        for (int i = 0; i < BB; i++){ P += sp[i]; Q += sq[i]; }
        const float inv = 1.0f / (float)(BB*HW);
        float mu  = P * inv;
        float var = Q * inv - mu*mu;
        float sc  = gamma[c] * rsqrtf(var + 1e-5f);
        g_scale[c] = sc;
        g_shift[c] = beta[c] - mu * sc;
    }
}

// ---------------- K2: a1 = l2norm(t_feature) rows ----------------
__global__ void k_a1(const float* __restrict__ t){
    int b = blockIdx.x; int tid = threadIdx.x;  // 128 threads
    float s = 0.f;
    for (int c = tid; c < CC; c += 128){ float x = t[b*CC + c]; s += x*x; }
    __shared__ float red[4];
    __shared__ float sinv;
    float ws = wredsum(s);
    if ((tid & 31) == 0) red[tid >> 5] = ws;
    __syncthreads();
    if (tid == 0) sinv = 1.0f / fmaxf(sqrtf(red[0]+red[1]+red[2]+red[3]), 1e-12f);
    __syncthreads();
    for (int c = tid; c < CC; c += 128) g_a1[b*CC + c] = t[b*CC + c] * sinv;
}

// ---------------- K3: fused main pass (448 threads, K-split x2, f32x2 FMA) ----------------
__global__ void __launch_bounds__(GT, 1) k_main(
    const float* __restrict__ v,
    const float* __restrict__ w,
    const float* __restrict__ wb)
{
    extern __shared__ float Xs[];
    __shared__ float pr[8*TT], pa[8*TT], satt[TT], sinv[TT];

    int b    = blockIdx.x / NTILE;
    int tile = blockIdx.x % NTILE;
    int hw0  = tile * TT;
    int tid  = threadIdx.x;

    // ---- fill smem with mvsa tile (swizzled, k-pair-interleaved) ----
    {
        int t  = tid % TT;
        int c0 = tid / TT;                  // 0..7
        const float* base = v + (size_t)b*CC*HW + hw0 + t;
        #pragma unroll 8
        for (int c = c0; c < CC; c += 8)
            Xs[sidx(c,t)] = base[(size_t)c*HW] * g_scale[c] + g_shift[c];
    }
    __syncthreads();

    // ---- per-pixel ||mvsa|| and att_map2 = dot(mvsa, a1)/||mvsa|| ----
    {
        int t = tid % TT;
        int s = tid / TT;                   // 8 slices of 64 channels
        const float* a1b = g_a1 + b*CC;
        float nr = 0.f, ad = 0.f;
        #pragma unroll 4
        for (int c = s*64; c < s*64 + 64; c++){
            float x = Xs[sidx(c,t)];
            nr = fmaf(x, x, nr);
            ad = fmaf(x, a1b[c], ad);
        }
        pr[s*TT + t] = nr;
        pa[s*TT + t] = ad;
    }
    __syncthreads();
    if (tid < TT){
        float nr = 0.f, ad = 0.f;
        #pragma unroll
        for (int s = 0; s < 8; s++){ nr += pr[s*TT + tid]; ad += pa[s*TT + tid]; }
        float a = ad / fmaxf(sqrtf(nr), 1e-12f);
        satt[tid] = a;
        g_att2[b*HW + hw0 + tid] = a;
    }
    // (no sync needed: GEMM only reads Xs; satt consumed after later syncs)

    // ---- GEMM: srea[64][56] = W[64,512] @ X[512,56], K split in 2 halves ----
    int kh = tid / 224;          // 0 or 1 (warps 0-6 / 7-13)
    int r  = tid % 224;
    int tn = r / NTILE;          // 0..15 -> 4 n-rows
    int tt = r % NTILE;          // 0..13 -> 4 pixels
    int n0 = tn*4, t0 = tt*4;

    unsigned long long acc[4][4];
    #pragma unroll
    for (int i = 0; i < 4; i++)
        #pragma unroll
        for (int j = 0; j < 4; j++) acc[i][j] = 0ull;

    const ulonglong2* wq0 = (const ulonglong2*)(w + (size_t)(n0+0)*CC);
    const ulonglong2* wq1 = (const ulonglong2*)(w + (size_t)(n0+1)*CC);
    const ulonglong2* wq2 = (const ulonglong2*)(w + (size_t)(n0+2)*CC);
    const ulonglong2* wq3 = (const ulonglong2*)(w + (size_t)(n0+3)*CC);

    int kb = kh * 64;            // first k4 (4-k group) of this half
    ulonglong2 wv0 = wq0[kb], wv1 = wq1[kb], wv2 = wq2[kb], wv3 = wq3[kb];
    int ubase = (kb*2)*28 + 2*tt;   // 16B-unit index for (k2 = 2*kb, pixel t0)

    #pragma unroll 2
    for (int k4 = 0; k4 < 64; k4++){
        int nidx = kb + ((k4 < 63) ? k4 + 1 : 63);
        ulonglong2 wn0 = wq0[nidx], wn1 = wq1[nidx], wn2 = wq2[nidx], wn3 = wq3[nidx];
        #pragma unroll
        for (int h = 0; h < 2; h++){
            int u  = ubase + h*28;
            int s0 = (u + (u>>3)) << 2;
            int u1 = u + 1;
            int s1 = (u1 + (u1>>3)) << 2;
            ulonglong2 xa = *(const ulonglong2*)(Xs + s0);   // k-pairs for px t0, t0+1
            ulonglong2 xb = *(const ulonglong2*)(Xs + s1);   // k-pairs for px t0+2, t0+3
            unsigned long long p0 = h ? wv0.y : wv0.x;
            unsigned long long p1 = h ? wv1.y : wv1.x;
            unsigned long long p2 = h ? wv2.y : wv2.x;
            unsigned long long p3 = h ? wv3.y : wv3.x;
            FMA2(acc[0][0], p0, xa.x); FMA2(acc[0][1], p0, xa.y);
            FMA2(acc[0][2], p0, xb.x); FMA2(acc[0][3], p0, xb.y);
            FMA2(acc[1][0], p1, xa.x); FMA2(acc[1][1], p1, xa.y);
            FMA2(acc[1][2], p1, xb.x); FMA2(acc[1][3], p1, xb.y);
            FMA2(acc[2][0], p2, xa.x); FMA2(acc[2][1], p2, xa.y);
            FMA2(acc[2][2], p2, xb.x); FMA2(acc[2][3], p2, xb.y);
            FMA2(acc[3][0], p3, xa.x); FMA2(acc[3][1], p3, xa.y);
            FMA2(acc[3][2], p3, xb.x); FMA2(acc[3][3], p3, xb.y);
        }
        ubase += 56;
        wv0 = wn0; wv1 = wn1; wv2 = wn2; wv3 = wn3;
    }

    // ---- combine halves, normalize over n, store, score partials ----
    __syncthreads();                        // all GEMM reads of Xs done
    float* comb  = Xs;                      // [64][56]
    float* pn    = Xs + NREG*TT;            // [16][56]
    float* stile = pn + 16*TT;              // [64][14]

    float s[4][4];
    #pragma unroll
    for (int i = 0; i < 4; i++)
        #pragma unroll
        for (int j = 0; j < 4; j++){
            float2 f = up2(acc[i][j]);
            s[i][j] = f.x + f.y;
        }

    if (kh == 1){
        #pragma unroll
        for (int i = 0; i < 4; i++){
            float4 o = make_float4(s[i][0], s[i][1], s[i][2], s[i][3]);
            *(float4*)&comb[(n0+i)*TT + t0] = o;
        }
    }
    __syncthreads();
    if (kh == 0){
        #pragma unroll
        for (int i = 0; i < 4; i++){
            float bi = wb[n0+i];
            #pragma unroll
            for (int j = 0; j < 4; j++) s[i][j] += comb[(n0+i)*TT + t0 + j] + bi;
        }
        #pragma unroll
        for (int j = 0; j < 4; j++){
            float ss = s[0][j]*s[0][j] + s[1][j]*s[1][j]
                     + s[2][j]*s[2][j] + s[3][j]*s[3][j];
            pn[tn*TT + t0 + j] = ss;
        }
    }
    __syncthreads();
    if (tid < TT){
        float ss = 0.f;
        #pragma unroll
        for (int g = 0; g < 16; g++) ss += pn[g*TT + tid];
        sinv[tid] = 1.0f / fmaxf(sqrtf(ss), 1e-12f);
    }
    __syncthreads();
    if (kh == 0){
        float* outb = g_srean + ((size_t)b*NREG)*HW + hw0;
        float a0 = satt[t0], a1v = satt[t0+1], a2 = satt[t0+2], a3 = satt[t0+3];
        float i0 = sinv[t0], i1 = sinv[t0+1], i2 = sinv[t0+2], i3 = sinv[t0+3];
        #pragma unroll
        for (int i = 0; i < 4; i++){
            float4 o;
            o.x = s[i][0]*i0; o.y = s[i][1]*i1; o.z = s[i][2]*i2; o.w = s[i][3]*i3;
            *(float4*)&outb[(size_t)(n0+i)*HW + t0] = o;
            stile[(n0+i)*NTILE + tt] = o.x*a0 + o.y*a1v + o.z*a2 + o.w*a3;
        }
    }
    __syncthreads();
    if (tid < NREG){
        float q = 0.f;
        #pragma unroll
        for (int tl = 0; tl < NTILE; tl++) q += stile[tid*NTILE + tl];
        g_scorep[(b*NTILE + tile)*NREG + tid] = q;
    }
}

// ---------------- K5: feat = pooled @ fc1_w^T + fc1_b ----------------
#define PS 513
__global__ void k_feat(const float* __restrict__ fw, const float* __restrict__ fb){
    extern __shared__ float sm[];
    float* pooled = sm;              // 64 * 513
    float* ws     = sm + BB*PS;      // 8 * 513
    int tid = threadIdx.x;           // 256
    int o0 = blockIdx.x * 8;         // 64 blocks

    for (int idx = tid; idx < BB*CC; idx += 256){
        int bb = idx >> 9, cc = idx & 511;
        pooled[bb*PS + cc] = g_rowsum[idx] * (1.0f/(float)HW) * g_scale[cc] + g_shift[cc];
    }
    for (int idx = tid; idx < 8*CC; idx += 256){
        int oo = idx >> 9, cc = idx & 511;
        ws[oo*PS + cc] = fw[(size_t)(o0+oo)*CC + cc];
    }
    __syncthreads();

    #pragma unroll
    for (int r = 0; r < 2; r++){
        int p  = tid*2 + r;
        int bb = p >> 3, oo = p & 7;
        float s = 0.f;
        #pragma unroll 8
        for (int k = 0; k < CC; k++) s = fmaf(pooled[bb*PS + k], ws[oo*PS + k], s);
        g_feat[bb*CC + (o0+oo)] = s + fb[o0+oo];
    }
}

// ---------------- K6: per-batch stats + loss terms ----------------
__global__ void k_loss(){
    int b = blockIdx.x; int tid = threadIdx.x;  // 256 threads
    __shared__ float ssc[NREG];
    __shared__ int s_nmax;
    __shared__ float red[8];
    if (tid < NREG){
        float sv = 0.f;
        #pragma unroll
        for (int tl = 0; tl < NTILE; tl++) sv += g_scorep[(b*NTILE + tl)*NREG + tid];
        ssc[tid] = sv;
    }
    __syncthreads();
    if (tid == 0){
        float m = 0.f;
        for (int n = 0; n < NREG; n++) m += ssc[n];
        m *= (1.0f/NREG);
        float bmax = ssc[0]; int imax = 0;
        float sp = 0.f, sq = 0.f;
        for (int n = 0; n < NREG; n++){
            float x = ssc[n];
            if (x > bmax){ bmax = x; imax = n; }
            if (x > m) sp += x; else sq += x;
        }
        sp *= (1.0f/NREG); sq *= (1.0f/NREG);
        float d = sq - sp;
        g_l3[b] = (d > 20.0f) ? d : log1pf(expf(d));
        s_nmax = imax;
    }
    __syncthreads();

    const float* pl = g_att2 + b*HW;
    const float* ql = g_srean + ((size_t)b*NREG + s_nmax)*HW;
    const float qs = 1.0f/(float)NREG;

    float mp = -1e30f, mq = -1e30f;
    for (int h = tid; h < HW; h += 256){
        mp = fmaxf(mp, pl[h]);
        mq = fmaxf(mq, ql[h]*qs);
    }
    mp = blockRedMax256(mp, red);
    mq = blockRedMax256(mq, red);

    float ep = 0.f, eq = 0.f;
    for (int h = tid; h < HW; h += 256){
        ep += expf(pl[h] - mp);
        eq += expf(ql[h]*qs - mq);
    }
    ep = blockRedSum256(ep, red);
    eq = blockRedSum256(eq, red);
    float lsep = mp + logf(ep);
    float lseq = mq + logf(eq);

    float S = 0.f;
    for (int h = tid; h < HW; h += 256){
        float lp = pl[h] - lsep;
        float lq = ql[h]*qs - lseq;
        float p  = expf(lp);
        float q  = expf(lq);
        float lm = logf(0.5f*(p + q));
        S += p*(lp - lm) + q*(lq - lm);
    }
    S = blockRedSum256(S, red);
    if (tid == 0) g_ls[b] = S;
}

// ---------------- K7: dual_sim = l2norm(feat) @ a1^T ----------------
__global__ void k_dual(float* __restrict__ out){
    int b = blockIdx.x; int tid = threadIdx.x;  // 128 threads
    __shared__ float fr[CC];
    __shared__ float red[4];
    __shared__ float sinvb;
    float ss = 0.f;
    for (int c = tid; c < CC; c += 128){ float x = g_feat[b*CC + c]; fr[c] = x; ss += x*x; }
    ss = wredsum(ss);
    if ((tid & 31) == 0) red[tid >> 5] = ss;
    __syncthreads();
    if (tid == 0) sinvb = 1.0f / fmaxf(sqrtf(red[0]+red[1]+red[2]+red[3]), 1e-12f);
    __syncthreads();
    int warp = tid >> 5, lane = tid & 31;
    for (int j = warp; j < BB; j += 4){
        const float* a = g_a1 + j*CC;
        float s = 0.f;
        for (int c = lane; c < CC; c += 32) s += fr[c] * a[c];
        s = wredsum(s);
        if (lane == 0) out[b*BB + j] = s * sinvb;
    }
}

// ---------------- K8: final scalar loss ----------------
__global__ void k_final(float* __restrict__ out, int li){
    int t = threadIdx.x;  // 64 threads
    __shared__ float r3[BB], rls[BB];
    r3[t] = g_l3[t]; rls[t] = g_ls[t];
    __syncthreads();
    if (t == 0){
        float a = 0.f, c2 = 0.f;
        for (int i = 0; i < BB; i++){ a += r3[i]; c2 += rls[i]; }
        float loss3 = a / (float)BB;
        float loss2 = 0.5f * c2 / (float)BB;
        out[li] = 0.1f*loss3 + 0.1f*loss2;
    }
}

// ---------------- launcher ----------------
extern "C" void kernel_launch(void* const* d_in, const int* in_sizes, int n_in,
                              void* d_out, int out_size){
    const float* v     = (const float*)d_in[0];
    const float* t     = (const float*)d_in[1];
    const float* cw    = (const float*)d_in[2];
    const float* cb    = (const float*)d_in[3];
    const float* gamma = (const float*)d_in[4];
    const float* beta  = (const float*)d_in[5];
    const float* fw    = (const float*)d_in[6];
    const float* fb    = (const float*)d_in[7];
    float* out = (float*)d_out;

    cudaFuncSetAttribute(k_main, cudaFuncAttributeMaxDynamicSharedMemorySize, XS_BYTES);
    cudaFuncSetAttribute(k_feat, cudaFuncAttributeMaxDynamicSharedMemorySize, (BB*PS + 8*PS)*4);

    k_rowsum<<<(BB*CC)/8, 256>>>(v);
    k_bnparam<<<CC, 64>>>(gamma, beta);
    k_a1<<<BB, 128>>>(t);
    k_main<<<BB*NTILE, GT, XS_BYTES>>>(v, cw, cb);
    k_feat<<<64, 256, (BB*PS + 8*PS)*4>>>(fw, fb);
    k_loss<<<BB, 256>>>();
    k_dual<<<BB, 128>>>(out);
    int li = (out_size > 4096) ? 4096 : (out_size - 1);
    k_final<<<1, 64>>>(out, li);
}